// round 11
// baseline (speedup 1.0000x reference)
#include <cuda_runtime.h>
#include <cuda_fp16.h>
#include <math.h>
#include <stdint.h>

#define N_TOKENS 16384
#define D_MODEL  4096
#define N_EXP    64
#define LB_COEF  0.01f

#define KC     32                 // k per chunk (two 16-k warpgroup halves)
#define NCHUNK (D_MODEL / KC)     // 128
#define TM     64
#define NCTA   (N_TOKENS / TM)    // 256
#define NTHR   256

// interleaved layout: row = 16 pair-words x {h1,h2} = 32 words + 8 pad = 40
#define PA      40
#define A_OFF   0
#define B_OFF   (64 * PA)          // 2560
#define STAGE_W (128 * PA)         // 5120 words = 20 KB
#define DYN_BYTES (2 * STAGE_W * 4)   // 40960 B (logits 64*65*4 fits)

#define WSCALE   256.0f
#define WDESCALE 0.00390625f       // 2^-8

// ---------------- helpers ----------------
// split float4 -> interleaved uint4s: q0 = {h1(k01), h2(k01), h1(k23), h2(k23)}
static __device__ __forceinline__ void split4i(float4 v, uint4& q) {
    __half a0 = __float2half_rn(v.x);
    __half a1 = __float2half_rn(v.y);
    __half a2 = __float2half_rn(v.z);
    __half a3 = __float2half_rn(v.w);
    __half b0 = __float2half_rn(v.x - __half2float(a0));
    __half b1 = __float2half_rn(v.y - __half2float(a1));
    __half b2 = __float2half_rn(v.z - __half2float(a2));
    __half b3 = __float2half_rn(v.w - __half2float(a3));
    __half2 p01 = __halves2half2(a0, a1);
    __half2 q01 = __halves2half2(b0, b1);
    __half2 p23 = __halves2half2(a2, a3);
    __half2 q23 = __halves2half2(b2, b3);
    q.x = *reinterpret_cast<uint32_t*>(&p01);
    q.y = *reinterpret_cast<uint32_t*>(&q01);
    q.z = *reinterpret_cast<uint32_t*>(&p23);
    q.w = *reinterpret_cast<uint32_t*>(&q23);
}

#define MMAH(d, a, b)                                                    \
    asm volatile(                                                        \
        "mma.sync.aligned.m16n8k16.row.col.f32.f16.f16.f32 "             \
        "{%0,%1,%2,%3}, {%4,%5,%6,%7}, {%8,%9}, {%0,%1,%2,%3};"          \
        : "+f"((d)[0]), "+f"((d)[1]), "+f"((d)[2]), "+f"((d)[3])         \
        : "r"((a)[0]), "r"((a)[1]), "r"((a)[2]), "r"((a)[3]),            \
          "r"((b)[0]), "r"((b)[1]))

// ---------------- device scratch (zero-initialized at module load) ----------------
__device__ float g_psum[N_EXP];
__device__ int   g_cnt[N_EXP];
__device__ int   g_ticket;

// ---------------- fused GEMM (2xFP16 3-term) + softmax/top2 + loss ----------------
// 256 threads = 8 warps, 2 CTAs/SM. CTA tile 64x64. Warp tile 32x32 over one k16.
__global__ __launch_bounds__(NTHR, 2)
void router_kernel(const float* __restrict__ x,
                   const float* __restrict__ gw,
                   float* __restrict__ out)
{
    extern __shared__ float dynsm[];
    __shared__ int   cb[N_EXP];
    __shared__ float s_red[N_EXP];
    __shared__ float s_m[TM];
    __shared__ float s_inv[TM];
    __shared__ int   s_islast;

    const int tid  = threadIdx.x;
    const int t0   = blockIdx.x * TM;
    const int lane = tid & 31;
    const int wid  = tid >> 5;
    const int wg   = wid >> 2;          // k16-half of chunk
    const int widg = wid & 3;
    const int wm   = widg >> 1;         // 0..1 -> token base wm*32
    const int wn   = widg & 1;          // 0..1 -> expert base wn*32
    const int lr   = lane >> 2;
    const int lc   = lane & 3;
    const int kw   = 2 * (wg * 8 + lc); // word offset of pair-word p within row

    if (tid < N_EXP) cb[tid] = 0;

    uint32_t* smw = (uint32_t*)dynsm;

    // fill mapping: row rA = tid>>2 (0..63), f4 slots sA and sA+4
    const int rA = tid >> 2;
    const int sA = tid & 3;

    const float4* x4 = (const float4*)x;     // row pitch 1024 f4
    const float4* w4 = (const float4*)gw;

    const size_t xo = (size_t)(t0 + rA) * 1024 + sA;
    const size_t wo = (size_t)rA        * 1024 + sA;

    float4 va0, va1, vb0, vb1;

    // ---- prologue: chunk 0 -> stage 0
    va0 = x4[xo]; va1 = x4[xo + 4];
    vb0 = w4[wo]; vb1 = w4[wo + 4];
    {
        uint32_t* s = smw;
        uint4 q;
        split4i(va0, q);
        *(uint4*)(s + A_OFF + rA * PA + 4 * sA) = q;
        split4i(va1, q);
        *(uint4*)(s + A_OFF + rA * PA + 4 * sA + 16) = q;
        split4i(make_float4(vb0.x * WSCALE, vb0.y * WSCALE, vb0.z * WSCALE, vb0.w * WSCALE), q);
        *(uint4*)(s + B_OFF + rA * PA + 4 * sA) = q;
        split4i(make_float4(vb1.x * WSCALE, vb1.y * WSCALE, vb1.z * WSCALE, vb1.w * WSCALE), q);
        *(uint4*)(s + B_OFF + rA * PA + 4 * sA + 16) = q;
    }
    __syncthreads();

    float acc[2][4][4];
#pragma unroll
    for (int mi = 0; mi < 2; mi++)
#pragma unroll
        for (int ni = 0; ni < 4; ni++)
#pragma unroll
            for (int j = 0; j < 4; j++) acc[mi][ni][j] = 0.0f;

    // ---- main loop: double-buffered, one bar per chunk
    for (int c = 0; c < NCHUNK; c++) {
        if (c + 1 < NCHUNK) {
            const size_t d = (size_t)(c + 1) * 8;
            va0 = x4[xo + d]; va1 = x4[xo + d + 4];
            vb0 = w4[wo + d]; vb1 = w4[wo + d + 4];
        }

        // compute on current stage (one k16 per warp)
        {
            const uint32_t* s = smw + (c & 1) * STAGE_W;
            uint32_t a1[2][4], a2[2][4];
#pragma unroll
            for (int mi = 0; mi < 2; mi++) {
                int ar = (wm * 32 + mi * 16 + lr) * PA + kw;
                uint2 u0 = *(const uint2*)(s + A_OFF + ar);
                uint2 u1 = *(const uint2*)(s + A_OFF + ar + 8 * PA);
                uint2 u2 = *(const uint2*)(s + A_OFF + ar + 8);
                uint2 u3 = *(const uint2*)(s + A_OFF + ar + 8 * PA + 8);
                a1[mi][0] = u0.x; a2[mi][0] = u0.y;
                a1[mi][1] = u1.x; a2[mi][1] = u1.y;
                a1[mi][2] = u2.x; a2[mi][2] = u2.y;
                a1[mi][3] = u3.x; a2[mi][3] = u3.y;
            }
#pragma unroll
            for (int ni = 0; ni < 4; ni++) {
                int br = (wn * 32 + ni * 8 + lr) * PA + kw;
                uint2 v0 = *(const uint2*)(s + B_OFF + br);
                uint2 v1 = *(const uint2*)(s + B_OFF + br + 8);
                uint32_t b1[2] = { v0.x, v1.x };
                uint32_t b2[2] = { v0.y, v1.y };
#pragma unroll
                for (int mi = 0; mi < 2; mi++) {
                    MMAH(acc[mi][ni], a1[mi], b1);
                    MMAH(acc[mi][ni], a2[mi], b1);
                    MMAH(acc[mi][ni], a1[mi], b2);
                    // a2*b2 dropped: ~2^-22 relative, below noise floor
                }
            }
        }

        // convert + store chunk c+1 into the other stage
        if (c + 1 < NCHUNK) {
            uint32_t* s = smw + ((c + 1) & 1) * STAGE_W;
            uint4 q;
            split4i(va0, q);
            *(uint4*)(s + A_OFF + rA * PA + 4 * sA) = q;
            split4i(va1, q);
            *(uint4*)(s + A_OFF + rA * PA + 4 * sA + 16) = q;
            split4i(make_float4(vb0.x * WSCALE, vb0.y * WSCALE, vb0.z * WSCALE, vb0.w * WSCALE), q);
            *(uint4*)(s + B_OFF + rA * PA + 4 * sA) = q;
            split4i(make_float4(vb1.x * WSCALE, vb1.y * WSCALE, vb1.z * WSCALE, vb1.w * WSCALE), q);
            *(uint4*)(s + B_OFF + rA * PA + 4 * sA + 16) = q;
        }
        __syncthreads();
    }

    // ---- merge k-half accumulators into G[64][65] (overlays stage smem)
    float* G = dynsm;
    if (wg == 0) {
#pragma unroll
        for (int mi = 0; mi < 2; mi++)
#pragma unroll
            for (int ni = 0; ni < 4; ni++) {
                int tr = wm * 32 + mi * 16 + lr;
                int ec = wn * 32 + ni * 8 + 2 * lc;
                G[tr * 65 + ec]           = acc[mi][ni][0] * WDESCALE;
                G[tr * 65 + ec + 1]       = acc[mi][ni][1] * WDESCALE;
                G[(tr + 8) * 65 + ec]     = acc[mi][ni][2] * WDESCALE;
                G[(tr + 8) * 65 + ec + 1] = acc[mi][ni][3] * WDESCALE;
            }
    }
    __syncthreads();
    if (wg == 1) {
#pragma unroll
        for (int mi = 0; mi < 2; mi++)
#pragma unroll
            for (int ni = 0; ni < 4; ni++) {
                int tr = wm * 32 + mi * 16 + lr;
                int ec = wn * 32 + ni * 8 + 2 * lc;
                G[tr * 65 + ec]           += acc[mi][ni][0] * WDESCALE;
                G[tr * 65 + ec + 1]       += acc[mi][ni][1] * WDESCALE;
                G[(tr + 8) * 65 + ec]     += acc[mi][ni][2] * WDESCALE;
                G[(tr + 8) * 65 + ec + 1] += acc[mi][ni][3] * WDESCALE;
            }
    }
    __syncthreads();

    // ---- epilogue phase 1: per-token max + top2 on logits
    int i1 = 0, i2 = 0;
    if (tid < TM) {
        const float* row = G + tid * 65;
        float v1 = -INFINITY, v2 = -INFINITY;
#pragma unroll 8
        for (int e = 0; e < N_EXP; e++) {
            float v = row[e];
            if (v > v1)      { v2 = v1; i2 = i1; v1 = v; i1 = e; }
            else if (v > v2) { v2 = v;  i2 = e; }
        }
        s_m[tid] = v1;   // max == top1
    }
    __syncthreads();

    // ---- phase 2: all 256 threads exponentiate (parallel MUFU)
#pragma unroll
    for (int i = 0; i < (TM * N_EXP) / NTHR; i++) {
        int idx = tid + i * NTHR;
        int t = idx >> 6, e = idx & 63;
        G[t * 65 + e] = expf(G[t * 65 + e] - s_m[t]);
    }
    __syncthreads();

    // ---- phase 3: per-token sums + outputs
    if (tid < TM) {
        const float* row = G + tid * 65;
        float ssum = 0.0f;
#pragma unroll 8
        for (int e = 0; e < N_EXP; e++) ssum += row[e];
        s_inv[tid] = 1.0f / ssum;

        float e1 = row[i1], e2 = row[i2];
        float rn = 1.0f / (e1 + e2);
        int tg = t0 + tid;
        out[2 * tg]     = e1 * rn;
        out[2 * tg + 1] = e2 * rn;
        out[2 * N_TOKENS + 2 * tg]     = (float)i1;
        out[2 * N_TOKENS + 2 * tg + 1] = (float)i2;
        atomicAdd(&cb[i1], 1);
    }
    __syncthreads();

    // ---- phase 4: per-expert prob sums -> global
    if (tid < N_EXP) {
        float s = 0.0f;
#pragma unroll 8
        for (int t = 0; t < TM; t++) s += G[t * 65 + tid] * s_inv[t];
        atomicAdd(&g_psum[tid], s);
        atomicAdd(&g_cnt[tid], cb[tid]);
    }

    // ---- last CTA: loss + scratch reset
    if (tid == 0) {
        __threadfence();
        int t = atomicAdd(&g_ticket, 1);
        s_islast = (t == NCTA - 1) ? 1 : 0;
    }
    __syncthreads();
    if (s_islast) {
        __threadfence();
        if (tid < N_EXP) {
            float p = *(volatile float*)&g_psum[tid];
            int   f = *(volatile int*)&g_cnt[tid];
            s_red[tid] = (float)f * p;
            g_psum[tid] = 0.0f;
            g_cnt[tid]  = 0;
        }
        __syncthreads();
        for (int st = 32; st > 0; st >>= 1) {
            if (tid < st) s_red[tid] += s_red[tid + st];
            __syncthreads();
        }
        if (tid == 0) {
            out[4 * N_TOKENS] = LB_COEF * s_red[0] * (1.0f / N_TOKENS) * (1.0f / N_TOKENS);
            g_ticket = 0;
        }
    }
}

// ---------------- launch ----------------
extern "C" void kernel_launch(void* const* d_in, const int* in_sizes, int n_in,
                              void* d_out, int out_size)
{
    const float* x  = (const float*)d_in[0];
    const float* gw = (const float*)d_in[1];
    float* out = (float*)d_out;

    cudaFuncSetAttribute(router_kernel,
                         cudaFuncAttributeMaxDynamicSharedMemorySize, DYN_BYTES);

    router_kernel<<<NCTA, NTHR, DYN_BYTES>>>(x, gw, out);
}

// round 12
// speedup vs baseline: 1.1624x; 1.1624x over previous
#include <cuda_runtime.h>
#include <cuda_fp16.h>
#include <math.h>
#include <stdint.h>

#define N_TOKENS 16384
#define D_MODEL  4096
#define N_EXP    64
#define LB_COEF  0.01f

#define NCH64  (D_MODEL / 64)      // 64 iterations of 64-k
#define TM     64
#define NCTA   (N_TOKENS / TM)     // 256
#define NTHR   256

// R10-proven sub-chunk layout (32 k): 4 regions of 64 rows x (16 pair-words + 4 pad)
#define PA      20
#define A1_OFF  0
#define A2_OFF  (64 * PA)          // 1280
#define B1_OFF  (2 * 64 * PA)      // 2560
#define B2_OFF  (3 * 64 * PA)      // 3840
#define SUB_W   (4 * 64 * PA)      // 5120 words = 20 KB
#define STAGE_W (2 * SUB_W)        // 10240 words = 40 KB (two 32-k subs)
#define DYN_BYTES (2 * STAGE_W * 4)   // 81920 B

#define WSCALE   256.0f
#define WDESCALE 0.00390625f       // 2^-8

// ---------------- helpers ----------------
static __device__ __forceinline__ uint32_t smem_u32(const void* p) {
    uint32_t a;
    asm("{ .reg .u64 t; cvta.to.shared.u64 t, %1; cvt.u32.u64 %0, t; }" : "=r"(a) : "l"(p));
    return a;
}
#define CPASYNC16(dst, src) \
    asm volatile("cp.async.cg.shared.global [%0], [%1], 16;" :: "r"(dst), "l"(src))
#define CPCOMMIT()  asm volatile("cp.async.commit_group;" ::: "memory")
#define CPWAIT0()   asm volatile("cp.async.wait_group 0;" ::: "memory")

// split float4 -> h1 pairs (uint2) + residual h2 pairs (uint2)
static __device__ __forceinline__ void split4(float4 v, uint2& h1, uint2& h2) {
    __half a0 = __float2half_rn(v.x);
    __half a1 = __float2half_rn(v.y);
    __half a2 = __float2half_rn(v.z);
    __half a3 = __float2half_rn(v.w);
    __half b0 = __float2half_rn(v.x - __half2float(a0));
    __half b1 = __float2half_rn(v.y - __half2float(a1));
    __half b2 = __float2half_rn(v.z - __half2float(a2));
    __half b3 = __float2half_rn(v.w - __half2float(a3));
    __half2 p01 = __halves2half2(a0, a1);
    __half2 p23 = __halves2half2(a2, a3);
    __half2 q01 = __halves2half2(b0, b1);
    __half2 q23 = __halves2half2(b2, b3);
    h1.x = *reinterpret_cast<uint32_t*>(&p01);
    h1.y = *reinterpret_cast<uint32_t*>(&p23);
    h2.x = *reinterpret_cast<uint32_t*>(&q01);
    h2.y = *reinterpret_cast<uint32_t*>(&q23);
}

#define MMAH(d, a, b)                                                    \
    asm volatile(                                                        \
        "mma.sync.aligned.m16n8k16.row.col.f32.f16.f16.f32 "             \
        "{%0,%1,%2,%3}, {%4,%5,%6,%7}, {%8,%9}, {%0,%1,%2,%3};"          \
        : "+f"((d)[0]), "+f"((d)[1]), "+f"((d)[2]), "+f"((d)[3])         \
        : "r"((a)[0]), "r"((a)[1]), "r"((a)[2]), "r"((a)[3]),            \
          "r"((b)[0]), "r"((b)[1]))

// ---------------- device scratch ----------------
__device__ uint32_t g_b1[N_EXP * (D_MODEL / 2)];   // pre-split gw*256, h1 pairs
__device__ uint32_t g_b2[N_EXP * (D_MODEL / 2)];   // residual h2 pairs
__device__ float g_psum[N_EXP];
__device__ int   g_cnt[N_EXP];
__device__ int   g_ticket;

// ---------------- prep: split gate_w*256 into f16 pair tables ----------------
__global__ void prep_kernel(const float* __restrict__ gw) {
    int i = blockIdx.x * blockDim.x + threadIdx.x;     // pair-word index
    if (i < N_EXP * (D_MODEL / 2)) {
        float x0 = gw[2 * i]     * WSCALE;
        float x1 = gw[2 * i + 1] * WSCALE;
        __half a0 = __float2half_rn(x0);
        __half a1 = __float2half_rn(x1);
        __half b0 = __float2half_rn(x0 - __half2float(a0));
        __half b1 = __float2half_rn(x1 - __half2float(a1));
        __half2 p = __halves2half2(a0, a1);
        __half2 q = __halves2half2(b0, b1);
        g_b1[i] = *reinterpret_cast<uint32_t*>(&p);
        g_b2[i] = *reinterpret_cast<uint32_t*>(&q);
    }
}

// ---------------- fused GEMM (2xFP16 3-term) + softmax/top2 + loss ----------------
// 256 threads = 8 warps, 2 CTAs/SM. CTA tile 64x64. Warp tile 32x32 over one k16.
__global__ __launch_bounds__(NTHR, 2)
void router_kernel(const float* __restrict__ x,
                   float* __restrict__ out)
{
    extern __shared__ float dynsm[];
    __shared__ int   cb[N_EXP];
    __shared__ float s_red[N_EXP];
    __shared__ float s_m[TM];
    __shared__ float s_inv[TM];
    __shared__ int   s_islast;

    const int tid  = threadIdx.x;
    const int t0   = blockIdx.x * TM;
    const int lane = tid & 31;
    const int wid  = tid >> 5;
    const int wg   = wid >> 2;          // k16-half within each 32-k sub-chunk
    const int widg = wid & 3;
    const int wm   = widg >> 1;
    const int wn   = widg & 1;
    const int lr   = lane >> 2;
    const int lc   = lane & 3;
    const int kp   = wg * 8 + lc;       // pair-word index within sub row

    if (tid < N_EXP) cb[tid] = 0;

    uint32_t* smw = (uint32_t*)dynsm;
    const uint32_t sbase = smem_u32(dynsm);

    // A fill mapping (R10): row rA = tid>>2, f4 slots sA and sA+4
    const int rA = tid >> 2;
    const int sA = tid & 3;
    // B cp.async mapping: row rB = tid>>2, 16B quarter qB = tid&3
    const int rB = rA, qB = sA;

    const float4* x4 = (const float4*)x;     // row pitch 1024 f4
    const size_t xo = (size_t)(t0 + rA) * 1024 + sA;

    // ---- prologue: fill stage 0 (subs q=0,1)
    {
        // B via cp.async
#pragma unroll
        for (int u = 0; u < 2; u++) {
            const uint32_t sd = sbase + (u * SUB_W) * 4;
            const uint32_t doff = (rB * PA + 4 * qB) * 4;
            const size_t so = (size_t)rB * (D_MODEL / 2) + u * 16 + 4 * qB;
            CPASYNC16(sd + B1_OFF * 4 + doff, g_b1 + so);
            CPASYNC16(sd + B2_OFF * 4 + doff, g_b2 + so);
        }
        CPCOMMIT();
        // A via LDG + split + STS
#pragma unroll
        for (int u = 0; u < 2; u++) {
            float4 v0 = x4[xo + u * 8];
            float4 v1 = x4[xo + u * 8 + 4];
            uint32_t* s = smw + u * SUB_W;
            uint2 h1, h2;
            split4(v0, h1, h2);
            *(uint2*)(s + A1_OFF + rA * PA + 2 * sA) = h1;
            *(uint2*)(s + A2_OFF + rA * PA + 2 * sA) = h2;
            split4(v1, h1, h2);
            *(uint2*)(s + A1_OFF + rA * PA + 2 * sA + 8) = h1;
            *(uint2*)(s + A2_OFF + rA * PA + 2 * sA + 8) = h2;
        }
        CPWAIT0();
    }
    __syncthreads();

    float acc[2][4][4];
#pragma unroll
    for (int mi = 0; mi < 2; mi++)
#pragma unroll
        for (int ni = 0; ni < 4; ni++)
#pragma unroll
            for (int j = 0; j < 4; j++) acc[mi][ni][j] = 0.0f;

    // ---- main loop: 64 iterations of 64-k, double-buffered, one bar each
    for (int c = 0; c < NCH64; c++) {
        float4 n0, n1, n2, n3;
        if (c + 1 < NCH64) {
            // B for next chunk via cp.async into free stage (buffer window = full iter)
            const uint32_t stb = sbase + (((c + 1) & 1) * STAGE_W) * 4;
#pragma unroll
            for (int u = 0; u < 2; u++) {
                const int q = 2 * (c + 1) + u;
                const uint32_t sd = stb + (u * SUB_W) * 4;
                const uint32_t doff = (rB * PA + 4 * qB) * 4;
                const size_t so = (size_t)rB * (D_MODEL / 2) + q * 16 + 4 * qB;
                CPASYNC16(sd + B1_OFF * 4 + doff, g_b1 + so);
                CPASYNC16(sd + B2_OFF * 4 + doff, g_b2 + so);
            }
            // A prefetch (4 independent LDG.128 -> MLP 4)
            const size_t d0 = (size_t)(2 * (c + 1)) * 8;
            n0 = x4[xo + d0];      n1 = x4[xo + d0 + 4];
            n2 = x4[xo + d0 + 8];  n3 = x4[xo + d0 + 12];
        }
        CPCOMMIT();

        // compute both 32-k subs of current stage
        const uint32_t* stg = smw + (c & 1) * STAGE_W;
#pragma unroll
        for (int u = 0; u < 2; u++) {
            const uint32_t* s = stg + u * SUB_W;
            uint32_t a1[2][4], a2[2][4];
#pragma unroll
            for (int mi = 0; mi < 2; mi++) {
                int ar = (wm * 32 + mi * 16 + lr) * PA + kp;
                a1[mi][0] = s[A1_OFF + ar];
                a1[mi][1] = s[A1_OFF + ar + 8 * PA];
                a1[mi][2] = s[A1_OFF + ar + 4];
                a1[mi][3] = s[A1_OFF + ar + 8 * PA + 4];
                a2[mi][0] = s[A2_OFF + ar];
                a2[mi][1] = s[A2_OFF + ar + 8 * PA];
                a2[mi][2] = s[A2_OFF + ar + 4];
                a2[mi][3] = s[A2_OFF + ar + 8 * PA + 4];
            }
#pragma unroll
            for (int ni = 0; ni < 4; ni++) {
                int br = (wn * 32 + ni * 8 + lr) * PA + kp;
                uint32_t b1[2] = { s[B1_OFF + br], s[B1_OFF + br + 4] };
                uint32_t b2[2] = { s[B2_OFF + br], s[B2_OFF + br + 4] };
#pragma unroll
                for (int mi = 0; mi < 2; mi++) {
                    MMAH(acc[mi][ni], a1[mi], b1);
                    MMAH(acc[mi][ni], a2[mi], b1);
                    MMAH(acc[mi][ni], a1[mi], b2);
                    // a2*b2 dropped: ~2^-22 relative, below noise floor
                }
            }
        }

        // A split + store for next chunk
        if (c + 1 < NCH64) {
            uint32_t* stn = smw + ((c + 1) & 1) * STAGE_W;
            uint2 h1, h2;
            uint32_t* s0 = stn;              // sub 0
            split4(n0, h1, h2);
            *(uint2*)(s0 + A1_OFF + rA * PA + 2 * sA) = h1;
            *(uint2*)(s0 + A2_OFF + rA * PA + 2 * sA) = h2;
            split4(n1, h1, h2);
            *(uint2*)(s0 + A1_OFF + rA * PA + 2 * sA + 8) = h1;
            *(uint2*)(s0 + A2_OFF + rA * PA + 2 * sA + 8) = h2;
            uint32_t* s1 = stn + SUB_W;      // sub 1
            split4(n2, h1, h2);
            *(uint2*)(s1 + A1_OFF + rA * PA + 2 * sA) = h1;
            *(uint2*)(s1 + A2_OFF + rA * PA + 2 * sA) = h2;
            split4(n3, h1, h2);
            *(uint2*)(s1 + A1_OFF + rA * PA + 2 * sA + 8) = h1;
            *(uint2*)(s1 + A2_OFF + rA * PA + 2 * sA + 8) = h2;
        }
        CPWAIT0();
        __syncthreads();
    }

    // ---- merge k-half accumulators into G[64][65] (overlays stage smem)
    float* G = dynsm;
    if (wg == 0) {
#pragma unroll
        for (int mi = 0; mi < 2; mi++)
#pragma unroll
            for (int ni = 0; ni < 4; ni++) {
                int tr = wm * 32 + mi * 16 + lr;
                int ec = wn * 32 + ni * 8 + 2 * lc;
                G[tr * 65 + ec]           = acc[mi][ni][0] * WDESCALE;
                G[tr * 65 + ec + 1]       = acc[mi][ni][1] * WDESCALE;
                G[(tr + 8) * 65 + ec]     = acc[mi][ni][2] * WDESCALE;
                G[(tr + 8) * 65 + ec + 1] = acc[mi][ni][3] * WDESCALE;
            }
    }
    __syncthreads();
    if (wg == 1) {
#pragma unroll
        for (int mi = 0; mi < 2; mi++)
#pragma unroll
            for (int ni = 0; ni < 4; ni++) {
                int tr = wm * 32 + mi * 16 + lr;
                int ec = wn * 32 + ni * 8 + 2 * lc;
                G[tr * 65 + ec]           += acc[mi][ni][0] * WDESCALE;
                G[tr * 65 + ec + 1]       += acc[mi][ni][1] * WDESCALE;
                G[(tr + 8) * 65 + ec]     += acc[mi][ni][2] * WDESCALE;
                G[(tr + 8) * 65 + ec + 1] += acc[mi][ni][3] * WDESCALE;
            }
    }
    __syncthreads();

    // ---- epilogue phase 1: per-token max + top2
    int i1 = 0, i2 = 0;
    if (tid < TM) {
        const float* row = G + tid * 65;
        float v1 = -INFINITY, v2 = -INFINITY;
#pragma unroll 8
        for (int e = 0; e < N_EXP; e++) {
            float v = row[e];
            if (v > v1)      { v2 = v1; i2 = i1; v1 = v; i1 = e; }
            else if (v > v2) { v2 = v;  i2 = e; }
        }
        s_m[tid] = v1;
    }
    __syncthreads();

    // ---- phase 2: all threads exponentiate
#pragma unroll
    for (int i = 0; i < (TM * N_EXP) / NTHR; i++) {
        int idx = tid + i * NTHR;
        int t = idx >> 6, e = idx & 63;
        G[t * 65 + e] = expf(G[t * 65 + e] - s_m[t]);
    }
    __syncthreads();

    // ---- phase 3: per-token sums + outputs
    if (tid < TM) {
        const float* row = G + tid * 65;
        float ssum = 0.0f;
#pragma unroll 8
        for (int e = 0; e < N_EXP; e++) ssum += row[e];
        s_inv[tid] = 1.0f / ssum;

        float e1 = row[i1], e2 = row[i2];
        float rn = 1.0f / (e1 + e2);
        int tg = t0 + tid;
        out[2 * tg]     = e1 * rn;
        out[2 * tg + 1] = e2 * rn;
        out[2 * N_TOKENS + 2 * tg]     = (float)i1;
        out[2 * N_TOKENS + 2 * tg + 1] = (float)i2;
        atomicAdd(&cb[i1], 1);
    }
    __syncthreads();

    // ---- phase 4: per-expert prob sums -> global
    if (tid < N_EXP) {
        float s = 0.0f;
#pragma unroll 8
        for (int t = 0; t < TM; t++) s += G[t * 65 + tid] * s_inv[t];
        atomicAdd(&g_psum[tid], s);
        atomicAdd(&g_cnt[tid], cb[tid]);
    }

    // ---- last CTA: loss + scratch reset
    if (tid == 0) {
        __threadfence();
        int t = atomicAdd(&g_ticket, 1);
        s_islast = (t == NCTA - 1) ? 1 : 0;
    }
    __syncthreads();
    if (s_islast) {
        __threadfence();
        if (tid < N_EXP) {
            float p = *(volatile float*)&g_psum[tid];
            int   f = *(volatile int*)&g_cnt[tid];
            s_red[tid] = (float)f * p;
            g_psum[tid] = 0.0f;
            g_cnt[tid]  = 0;
        }
        __syncthreads();
        for (int st = 32; st > 0; st >>= 1) {
            if (tid < st) s_red[tid] += s_red[tid + st];
            __syncthreads();
        }
        if (tid == 0) {
            out[4 * N_TOKENS] = LB_COEF * s_red[0] * (1.0f / N_TOKENS) * (1.0f / N_TOKENS);
            g_ticket = 0;
        }
    }
}

// ---------------- launch ----------------
extern "C" void kernel_launch(void* const* d_in, const int* in_sizes, int n_in,
                              void* d_out, int out_size)
{
    const float* x  = (const float*)d_in[0];
    const float* gw = (const float*)d_in[1];
    float* out = (float*)d_out;

    cudaFuncSetAttribute(router_kernel,
                         cudaFuncAttributeMaxDynamicSharedMemorySize, DYN_BYTES);

    prep_kernel<<<(N_EXP * (D_MODEL / 2) + 255) / 256, 256>>>(gw);
    router_kernel<<<NCTA, NTHR, DYN_BYTES>>>(x, out);
}

// round 13
// speedup vs baseline: 1.3047x; 1.1225x over previous
#include <cuda_runtime.h>
#include <cuda_fp16.h>
#include <math.h>
#include <stdint.h>

#define N_TOKENS 16384
#define D_MODEL  4096
#define N_EXP    64
#define LB_COEF  0.01f

#define NCH64  (D_MODEL / 64)      // 64 iterations of 64-k
#define TM     64
#define NCTA   (N_TOKENS / TM)     // 256
#define NTHR   256

// R10-proven sub-chunk layout (32 k): 4 regions of 64 rows x (16 pair-words + 4 pad)
#define PA      20
#define A1_OFF  0
#define A2_OFF  (64 * PA)          // 1280
#define B1_OFF  (2 * 64 * PA)      // 2560
#define B2_OFF  (3 * 64 * PA)      // 3840
#define SUB_W   (4 * 64 * PA)      // 5120 words = 20 KB
#define STAGE_W (2 * SUB_W)        // 10240 words = 40 KB (two 32-k subs)
#define DYN_BYTES (2 * STAGE_W * 4)   // 81920 B

#define WSCALE   256.0f
#define WDESCALE 0.00390625f       // 2^-8

// ---------------- helpers ----------------
static __device__ __forceinline__ uint32_t smem_u32(const void* p) {
    uint32_t a;
    asm("{ .reg .u64 t; cvta.to.shared.u64 t, %1; cvt.u32.u64 %0, t; }" : "=r"(a) : "l"(p));
    return a;
}
#define CPASYNC16(dst, src) \
    asm volatile("cp.async.cg.shared.global [%0], [%1], 16;" :: "r"(dst), "l"(src))
#define CPCOMMIT()  asm volatile("cp.async.commit_group;" ::: "memory")
#define CPWAIT0()   asm volatile("cp.async.wait_group 0;" ::: "memory")

#define LDSM4(r, addr)                                                        \
    asm volatile("ldmatrix.sync.aligned.m8n8.x4.shared.b16 {%0,%1,%2,%3}, [%4];" \
        : "=r"((r)[0]), "=r"((r)[1]), "=r"((r)[2]), "=r"((r)[3]) : "r"(addr))

// split float4 -> h1 pairs (uint2) + residual h2 pairs (uint2)
static __device__ __forceinline__ void split4(float4 v, uint2& h1, uint2& h2) {
    __half a0 = __float2half_rn(v.x);
    __half a1 = __float2half_rn(v.y);
    __half a2 = __float2half_rn(v.z);
    __half a3 = __float2half_rn(v.w);
    __half b0 = __float2half_rn(v.x - __half2float(a0));
    __half b1 = __float2half_rn(v.y - __half2float(a1));
    __half b2 = __float2half_rn(v.z - __half2float(a2));
    __half b3 = __float2half_rn(v.w - __half2float(a3));
    __half2 p01 = __halves2half2(a0, a1);
    __half2 p23 = __halves2half2(a2, a3);
    __half2 q01 = __halves2half2(b0, b1);
    __half2 q23 = __halves2half2(b2, b3);
    h1.x = *reinterpret_cast<uint32_t*>(&p01);
    h1.y = *reinterpret_cast<uint32_t*>(&p23);
    h2.x = *reinterpret_cast<uint32_t*>(&q01);
    h2.y = *reinterpret_cast<uint32_t*>(&q23);
}

#define MMAH(d, a, b)                                                    \
    asm volatile(                                                        \
        "mma.sync.aligned.m16n8k16.row.col.f32.f16.f16.f32 "             \
        "{%0,%1,%2,%3}, {%4,%5,%6,%7}, {%8,%9}, {%0,%1,%2,%3};"          \
        : "+f"((d)[0]), "+f"((d)[1]), "+f"((d)[2]), "+f"((d)[3])         \
        : "r"((a)[0]), "r"((a)[1]), "r"((a)[2]), "r"((a)[3]),            \
          "r"((b)[0]), "r"((b)[1]))

// ---------------- device scratch ----------------
__device__ uint32_t g_b1[N_EXP * (D_MODEL / 2)];   // pre-split gw*256, h1 pairs
__device__ uint32_t g_b2[N_EXP * (D_MODEL / 2)];   // residual h2 pairs
__device__ float g_psum[N_EXP];
__device__ int   g_cnt[N_EXP];
__device__ int   g_ticket;

// ---------------- prep: split gate_w*256 into f16 pair tables ----------------
__global__ void prep_kernel(const float* __restrict__ gw) {
    int i = blockIdx.x * blockDim.x + threadIdx.x;     // pair-word index
    if (i < N_EXP * (D_MODEL / 2)) {
        float x0 = gw[2 * i]     * WSCALE;
        float x1 = gw[2 * i + 1] * WSCALE;
        __half a0 = __float2half_rn(x0);
        __half a1 = __float2half_rn(x1);
        __half b0 = __float2half_rn(x0 - __half2float(a0));
        __half b1 = __float2half_rn(x1 - __half2float(a1));
        __half2 p = __halves2half2(a0, a1);
        __half2 q = __halves2half2(b0, b1);
        g_b1[i] = *reinterpret_cast<uint32_t*>(&p);
        g_b2[i] = *reinterpret_cast<uint32_t*>(&q);
    }
}

// ---------------- fused GEMM (2xFP16 3-term, ldmatrix) + softmax/top2 + loss ----
// 256 threads = 8 warps, 2 CTAs/SM. CTA tile 64x64. Warp tile 32x32 over one k16.
__global__ __launch_bounds__(NTHR, 2)
void router_kernel(const float* __restrict__ x,
                   float* __restrict__ out)
{
    extern __shared__ float dynsm[];
    __shared__ int   cb[N_EXP];
    __shared__ float s_red[N_EXP];
    __shared__ float s_m[TM];
    __shared__ float s_inv[TM];
    __shared__ int   s_islast;

    const int tid  = threadIdx.x;
    const int t0   = blockIdx.x * TM;
    const int lane = tid & 31;
    const int wid  = tid >> 5;
    const int wg   = wid >> 2;          // k16-half within each 32-k sub-chunk
    const int widg = wid & 3;
    const int wm   = widg >> 1;
    const int wn   = widg & 1;
    const int lr   = lane >> 2;
    const int lc   = lane & 3;

    if (tid < N_EXP) cb[tid] = 0;

    uint32_t* smw = (uint32_t*)dynsm;
    const uint32_t sbase = smem_u32(dynsm);

    // ---- loop-invariant ldmatrix lane addresses (byte offsets within a sub)
    // A (m16k16, x4): lanes 0-15 -> rows m0+0..15 koff0; 16-31 -> same rows koff 8 halves
    const int aRow = wm * 32 + (lane & 15);
    const uint32_t aBase = sbase + (uint32_t)((aRow * PA + wg * 8) * 4) + ((lane >> 4) << 4);
    // B (two n8k16 frags per x4): lanes 0-7 n0 rows koff0; 8-15 n0 koff1; 16-23 n0+8 koff0; 24-31 n0+8 koff1
    const int bRow = wn * 32 + ((lane >> 4) << 3) + (lane & 7);
    const uint32_t bBase = sbase + (uint32_t)((bRow * PA + wg * 8) * 4) + (((lane >> 3) & 1) << 4);

    const uint32_t aA1 = aBase + A1_OFF * 4;
    const uint32_t aA2 = aBase + A2_OFF * 4;
    const uint32_t bB1 = bBase + B1_OFF * 4;
    const uint32_t bB2 = bBase + B2_OFF * 4;
    const uint32_t MI_STEP = 16 * PA * 4;   // +16 rows (mi=1 / ni pair 2,3)

    // A fill mapping (R10): row rA = tid>>2, f4 slots sA and sA+4
    const int rA = tid >> 2;
    const int sA = tid & 3;
    const int rB = rA, qB = sA;

    const float4* x4 = (const float4*)x;     // row pitch 1024 f4
    const size_t xo = (size_t)(t0 + rA) * 1024 + sA;

    // ---- prologue: fill stage 0 (subs u=0,1)
    {
#pragma unroll
        for (int u = 0; u < 2; u++) {
            const uint32_t sd = sbase + (u * SUB_W) * 4;
            const uint32_t doff = (rB * PA + 4 * qB) * 4;
            const size_t so = (size_t)rB * (D_MODEL / 2) + u * 16 + 4 * qB;
            CPASYNC16(sd + B1_OFF * 4 + doff, g_b1 + so);
            CPASYNC16(sd + B2_OFF * 4 + doff, g_b2 + so);
        }
        CPCOMMIT();
#pragma unroll
        for (int u = 0; u < 2; u++) {
            float4 v0 = x4[xo + u * 8];
            float4 v1 = x4[xo + u * 8 + 4];
            uint32_t* s = smw + u * SUB_W;
            uint2 h1, h2;
            split4(v0, h1, h2);
            *(uint2*)(s + A1_OFF + rA * PA + 2 * sA) = h1;
            *(uint2*)(s + A2_OFF + rA * PA + 2 * sA) = h2;
            split4(v1, h1, h2);
            *(uint2*)(s + A1_OFF + rA * PA + 2 * sA + 8) = h1;
            *(uint2*)(s + A2_OFF + rA * PA + 2 * sA + 8) = h2;
        }
        CPWAIT0();
    }
    __syncthreads();

    float acc[2][4][4];
#pragma unroll
    for (int mi = 0; mi < 2; mi++)
#pragma unroll
        for (int ni = 0; ni < 4; ni++)
#pragma unroll
            for (int j = 0; j < 4; j++) acc[mi][ni][j] = 0.0f;

    // ---- main loop: 64 iterations of 64-k, double-buffered, one bar each
    for (int c = 0; c < NCH64; c++) {
        float4 n0, n1, n2, n3;
        if (c + 1 < NCH64) {
            const uint32_t stb = sbase + (((c + 1) & 1) * STAGE_W) * 4;
#pragma unroll
            for (int u = 0; u < 2; u++) {
                const int q = 2 * (c + 1) + u;
                const uint32_t sd = stb + (u * SUB_W) * 4;
                const uint32_t doff = (rB * PA + 4 * qB) * 4;
                const size_t so = (size_t)rB * (D_MODEL / 2) + q * 16 + 4 * qB;
                CPASYNC16(sd + B1_OFF * 4 + doff, g_b1 + so);
                CPASYNC16(sd + B2_OFF * 4 + doff, g_b2 + so);
            }
            const size_t d0 = (size_t)(2 * (c + 1)) * 8;
            n0 = x4[xo + d0];      n1 = x4[xo + d0 + 4];
            n2 = x4[xo + d0 + 8];  n3 = x4[xo + d0 + 12];
        }
        CPCOMMIT();

        // compute both 32-k subs of current stage via ldmatrix
        const uint32_t stoff = ((c & 1) * STAGE_W) * 4;
#pragma unroll
        for (int u = 0; u < 2; u++) {
            const uint32_t so = stoff + (u * SUB_W) * 4;
            uint32_t a1[2][4], a2[2][4], bq1[2][4], bq2[2][4];
            LDSM4(a1[0], aA1 + so);
            LDSM4(a1[1], aA1 + so + MI_STEP);
            LDSM4(a2[0], aA2 + so);
            LDSM4(a2[1], aA2 + so + MI_STEP);
            LDSM4(bq1[0], bB1 + so);            // ni 0,1 (n+0, n+8)
            LDSM4(bq1[1], bB1 + so + MI_STEP);  // ni 2,3 (n+16, n+24)
            LDSM4(bq2[0], bB2 + so);
            LDSM4(bq2[1], bB2 + so + MI_STEP);
#pragma unroll
            for (int ni = 0; ni < 4; ni++) {
                uint32_t b1[2] = { bq1[ni >> 1][(ni & 1) * 2], bq1[ni >> 1][(ni & 1) * 2 + 1] };
                uint32_t b2[2] = { bq2[ni >> 1][(ni & 1) * 2], bq2[ni >> 1][(ni & 1) * 2 + 1] };
#pragma unroll
                for (int mi = 0; mi < 2; mi++) {
                    MMAH(acc[mi][ni], a1[mi], b1);
                    MMAH(acc[mi][ni], a2[mi], b1);
                    MMAH(acc[mi][ni], a1[mi], b2);
                    // a2*b2 dropped: ~2^-22 relative, below noise floor
                }
            }
        }

        // A split + store for next chunk
        if (c + 1 < NCH64) {
            uint32_t* stn = smw + ((c + 1) & 1) * STAGE_W;
            uint2 h1, h2;
            uint32_t* s0 = stn;
            split4(n0, h1, h2);
            *(uint2*)(s0 + A1_OFF + rA * PA + 2 * sA) = h1;
            *(uint2*)(s0 + A2_OFF + rA * PA + 2 * sA) = h2;
            split4(n1, h1, h2);
            *(uint2*)(s0 + A1_OFF + rA * PA + 2 * sA + 8) = h1;
            *(uint2*)(s0 + A2_OFF + rA * PA + 2 * sA + 8) = h2;
            uint32_t* s1 = stn + SUB_W;
            split4(n2, h1, h2);
            *(uint2*)(s1 + A1_OFF + rA * PA + 2 * sA) = h1;
            *(uint2*)(s1 + A2_OFF + rA * PA + 2 * sA) = h2;
            split4(n3, h1, h2);
            *(uint2*)(s1 + A1_OFF + rA * PA + 2 * sA + 8) = h1;
            *(uint2*)(s1 + A2_OFF + rA * PA + 2 * sA + 8) = h2;
        }
        CPWAIT0();
        __syncthreads();
    }

    // ---- merge k-half accumulators into G[64][65] (overlays stage smem)
    float* G = dynsm;
    if (wg == 0) {
#pragma unroll
        for (int mi = 0; mi < 2; mi++)
#pragma unroll
            for (int ni = 0; ni < 4; ni++) {
                int tr = wm * 32 + mi * 16 + lr;
                int ec = wn * 32 + ni * 8 + 2 * lc;
                G[tr * 65 + ec]           = acc[mi][ni][0] * WDESCALE;
                G[tr * 65 + ec + 1]       = acc[mi][ni][1] * WDESCALE;
                G[(tr + 8) * 65 + ec]     = acc[mi][ni][2] * WDESCALE;
                G[(tr + 8) * 65 + ec + 1] = acc[mi][ni][3] * WDESCALE;
            }
    }
    __syncthreads();
    if (wg == 1) {
#pragma unroll
        for (int mi = 0; mi < 2; mi++)
#pragma unroll
            for (int ni = 0; ni < 4; ni++) {
                int tr = wm * 32 + mi * 16 + lr;
                int ec = wn * 32 + ni * 8 + 2 * lc;
                G[tr * 65 + ec]           += acc[mi][ni][0] * WDESCALE;
                G[tr * 65 + ec + 1]       += acc[mi][ni][1] * WDESCALE;
                G[(tr + 8) * 65 + ec]     += acc[mi][ni][2] * WDESCALE;
                G[(tr + 8) * 65 + ec + 1] += acc[mi][ni][3] * WDESCALE;
            }
    }
    __syncthreads();

    // ---- epilogue phase 1: per-token max + top2
    int i1 = 0, i2 = 0;
    if (tid < TM) {
        const float* row = G + tid * 65;
        float v1 = -INFINITY, v2 = -INFINITY;
#pragma unroll 8
        for (int e = 0; e < N_EXP; e++) {
            float v = row[e];
            if (v > v1)      { v2 = v1; i2 = i1; v1 = v; i1 = e; }
            else if (v > v2) { v2 = v;  i2 = e; }
        }
        s_m[tid] = v1;
    }
    __syncthreads();

    // ---- phase 2: all threads exponentiate
#pragma unroll
    for (int i = 0; i < (TM * N_EXP) / NTHR; i++) {
        int idx = tid + i * NTHR;
        int t = idx >> 6, e = idx & 63;
        G[t * 65 + e] = expf(G[t * 65 + e] - s_m[t]);
    }
    __syncthreads();

    // ---- phase 3: per-token sums + outputs
    if (tid < TM) {
        const float* row = G + tid * 65;
        float ssum = 0.0f;
#pragma unroll 8
        for (int e = 0; e < N_EXP; e++) ssum += row[e];
        s_inv[tid] = 1.0f / ssum;

        float e1 = row[i1], e2 = row[i2];
        float rn = 1.0f / (e1 + e2);
        int tg = t0 + tid;
        out[2 * tg]     = e1 * rn;
        out[2 * tg + 1] = e2 * rn;
        out[2 * N_TOKENS + 2 * tg]     = (float)i1;
        out[2 * N_TOKENS + 2 * tg + 1] = (float)i2;
        atomicAdd(&cb[i1], 1);
    }
    __syncthreads();

    // ---- phase 4: per-expert prob sums -> global
    if (tid < N_EXP) {
        float s = 0.0f;
#pragma unroll 8
        for (int t = 0; t < TM; t++) s += G[t * 65 + tid] * s_inv[t];
        atomicAdd(&g_psum[tid], s);
        atomicAdd(&g_cnt[tid], cb[tid]);
    }

    // ---- last CTA: loss + scratch reset
    if (tid == 0) {
        __threadfence();
        int t = atomicAdd(&g_ticket, 1);
        s_islast = (t == NCTA - 1) ? 1 : 0;
    }
    __syncthreads();
    if (s_islast) {
        __threadfence();
        if (tid < N_EXP) {
            float p = *(volatile float*)&g_psum[tid];
            int   f = *(volatile int*)&g_cnt[tid];
            s_red[tid] = (float)f * p;
            g_psum[tid] = 0.0f;
            g_cnt[tid]  = 0;
        }
        __syncthreads();
        for (int st = 32; st > 0; st >>= 1) {
            if (tid < st) s_red[tid] += s_red[tid + st];
            __syncthreads();
        }
        if (tid == 0) {
            out[4 * N_TOKENS] = LB_COEF * s_red[0] * (1.0f / N_TOKENS) * (1.0f / N_TOKENS);
            g_ticket = 0;
        }
    }
}

// ---------------- launch ----------------
extern "C" void kernel_launch(void* const* d_in, const int* in_sizes, int n_in,
                              void* d_out, int out_size)
{
    const float* x  = (const float*)d_in[0];
    const float* gw = (const float*)d_in[1];
    float* out = (float*)d_out;

    cudaFuncSetAttribute(router_kernel,
                         cudaFuncAttributeMaxDynamicSharedMemorySize, DYN_BYTES);

    prep_kernel<<<(N_EXP * (D_MODEL / 2) + 255) / 256, 256>>>(gw);
    router_kernel<<<NCTA, NTHR, DYN_BYTES>>>(x, out);
}